// round 6
// baseline (speedup 1.0000x reference)
#include <cuda_runtime.h>
#include <cstdint>
#include <cstddef>

#define SS 2048
#define DD 64
#define HH 16

static __device__ __forceinline__ float2 ffma2(float2 a, float2 b, float2 c) {
    unsigned long long ua = *reinterpret_cast<unsigned long long*>(&a);
    unsigned long long ub = *reinterpret_cast<unsigned long long*>(&b);
    unsigned long long uc = *reinterpret_cast<unsigned long long*>(&c);
    unsigned long long ud;
    asm("fma.rn.f32x2 %0, %1, %2, %3;" : "=l"(ud) : "l"(ua), "l"(ub), "l"(uc));
    return *reinterpret_cast<float2*>(&ud);
}

// T5 bidirectional bucket, NUM_BUCKETS=32, MAX_DISTANCE=128 (exact int thresholds)
static __device__ __forceinline__ int rp_bucket(int rel) {
    int n = -rel;
    int ret = (n < 0) ? 16 : 0;
    n = abs(n);
    if (n < 8) return ret + n;
    return ret + 8 + (n >= 12) + (n >= 16) + (n >= 23) + (n >= 32)
                   + (n >= 46) + (n >= 64) + (n >= 91);
}

// ---------------- K1: scores = QK^T/8 + bias, masked -> attn(pre), pb ------
__global__ __launch_bounds__(256) void k1_scores(
    const float* __restrict__ qg, const float* __restrict__ kg,
    const float* __restrict__ bw, const int* __restrict__ ctx,
    const int* __restrict__ mem, const unsigned int* __restrict__ mask,
    float* __restrict__ attn, float* __restrict__ pb)
{
    extern __shared__ float smx[];
    float* Qs = smx;               // [64][132] d-major, swizzled rows
    float* Ks = smx + 64 * 132;
    __shared__ float bwsh[32];

    const int tid = threadIdx.x;
    const int kt = blockIdx.x, qt = blockIdx.y, bh = blockIdx.z;
    const int b = bh >> 4, h = bh & 15;
    if (tid < 32) bwsh[tid] = bw[tid * HH + h];

    const float4* qv = (const float4*)(qg + ((size_t)bh * SS + (size_t)qt * 128) * DD);
    const float4* kv = (const float4*)(kg + ((size_t)bh * SS + (size_t)kt * 128) * DD);
#pragma unroll
    for (int rep = 0; rep < 8; rep++) {
        int i4 = rep * 256 + tid;
        int row = i4 >> 4;
        int c4 = (i4 & 15) << 2;
        float4 a = qv[i4], bv = kv[i4];
        int r = row ^ (((c4 >> 2) & 7) << 2);
        Qs[(c4+0)*132 + r] = a.x;  Qs[(c4+1)*132 + r] = a.y;
        Qs[(c4+2)*132 + r] = a.z;  Qs[(c4+3)*132 + r] = a.w;
        Ks[(c4+0)*132 + r] = bv.x; Ks[(c4+1)*132 + r] = bv.y;
        Ks[(c4+2)*132 + r] = bv.z; Ks[(c4+3)*132 + r] = bv.w;
    }
    __syncthreads();

    const int ty = tid >> 4, tx = tid & 15;
    const int qr = ty << 3, kc = tx << 3;
    float2 acc[8][4];
#pragma unroll
    for (int i = 0; i < 8; i++)
#pragma unroll
        for (int j = 0; j < 4; j++) acc[i][j] = make_float2(0.f, 0.f);

#pragma unroll 8
    for (int d = 0; d < 64; d++) {
        const float* Qd = Qs + d * 132;
        const float* Kd = Ks + d * 132;
        int fd = ((d >> 2) & 7) << 2;
        int rq = qr ^ fd, rk = kc ^ fd;
        float4 a0 = *(const float4*)(Qd + rq);
        float4 a1 = *(const float4*)(Qd + (rq ^ 4));
        float4 b0 = *(const float4*)(Kd + rk);
        float4 b1 = *(const float4*)(Kd + (rk ^ 4));
        float2 bp0 = make_float2(b0.x, b0.y), bp1 = make_float2(b0.z, b0.w);
        float2 bp2 = make_float2(b1.x, b1.y), bp3 = make_float2(b1.z, b1.w);
        float av[8] = {a0.x,a0.y,a0.z,a0.w,a1.x,a1.y,a1.z,a1.w};
#pragma unroll
        for (int i = 0; i < 8; i++) {
            float2 ap = make_float2(av[i], av[i]);
            acc[i][0] = ffma2(ap, bp0, acc[i][0]);
            acc[i][1] = ffma2(ap, bp1, acc[i][1]);
            acc[i][2] = ffma2(ap, bp2, acc[i][2]);
            acc[i][3] = ffma2(ap, bp3, acc[i][3]);
        }
    }

    const int qi0 = qt * 128 + qr;
    const int kj0 = kt * 128 + kc;
    int ctxv[8], memv[8];
#pragma unroll
    for (int i = 0; i < 8; i++) ctxv[i] = ctx[b * SS + qi0 + i];
#pragma unroll
    for (int j = 0; j < 8; j++) memv[j] = mem[b * SS + kj0 + j];

#pragma unroll
    for (int i = 0; i < 8; i++) {
        const int qi = qi0 + i;
        const size_t off = ((size_t)bh * SS + qi) * SS + kj0;
        // mask: one 32-bit word per element (works for int32 0/1 and f32 0.0/1.0)
        const uint4 m0 = *(const uint4*)(mask + ((size_t)b * SS + qi) * SS + kj0);
        const uint4 m1 = *(const uint4*)(mask + ((size_t)b * SS + qi) * SS + kj0 + 4);
        unsigned int mw[8] = {m0.x, m0.y, m0.z, m0.w, m1.x, m1.y, m1.z, m1.w};
        float sv[8], pv[8];
#pragma unroll
        for (int j = 0; j < 8; j++) {
            float bias = bwsh[rp_bucket(memv[j] - ctxv[i])];
            pv[j] = bias;
            float s = ((j & 1) ? acc[i][j >> 1].y : acc[i][j >> 1].x) * 0.125f + bias;
            sv[j] = (mw[j] != 0u) ? -1.0e9f : s;
        }
        *(float4*)(attn + off)     = make_float4(sv[0], sv[1], sv[2], sv[3]);
        *(float4*)(attn + off + 4) = make_float4(sv[4], sv[5], sv[6], sv[7]);
        *(float4*)(pb + off)       = make_float4(pv[0], pv[1], pv[2], pv[3]);
        *(float4*)(pb + off + 4)   = make_float4(pv[4], pv[5], pv[6], pv[7]);
    }
}

// ---------------- K2: in-place row softmax over 2048 cols ------------------
__global__ __launch_bounds__(256) void k2_softmax(float* __restrict__ attn)
{
    __shared__ float red[8];
    float4* p = (float4*)(attn + (size_t)blockIdx.x * SS);
    const int tid = threadIdx.x;
    float4 x0 = p[tid], x1 = p[tid + 256];

    float m = fmaxf(fmaxf(fmaxf(x0.x, x0.y), fmaxf(x0.z, x0.w)),
                    fmaxf(fmaxf(x1.x, x1.y), fmaxf(x1.z, x1.w)));
#pragma unroll
    for (int o = 16; o; o >>= 1) m = fmaxf(m, __shfl_xor_sync(~0u, m, o));
    if ((tid & 31) == 0) red[tid >> 5] = m;
    __syncthreads();
    if (tid < 32) {
        float t = red[tid & 7];
#pragma unroll
        for (int o = 4; o; o >>= 1) t = fmaxf(t, __shfl_xor_sync(~0u, t, o));
        if (tid == 0) red[0] = t;
    }
    __syncthreads();
    m = red[0];
    __syncthreads();

    x0.x = __expf(x0.x - m); x0.y = __expf(x0.y - m);
    x0.z = __expf(x0.z - m); x0.w = __expf(x0.w - m);
    x1.x = __expf(x1.x - m); x1.y = __expf(x1.y - m);
    x1.z = __expf(x1.z - m); x1.w = __expf(x1.w - m);
    float s = x0.x + x0.y + x0.z + x0.w + x1.x + x1.y + x1.z + x1.w;
#pragma unroll
    for (int o = 16; o; o >>= 1) s += __shfl_xor_sync(~0u, s, o);
    if ((tid & 31) == 0) red[tid >> 5] = s;
    __syncthreads();
    if (tid < 32) {
        float t = red[tid & 7];
#pragma unroll
        for (int o = 4; o; o >>= 1) t += __shfl_xor_sync(~0u, t, o);
        if (tid == 0) red[0] = t;
    }
    __syncthreads();
    float inv = 1.0f / red[0];

    x0.x *= inv; x0.y *= inv; x0.z *= inv; x0.w *= inv;
    x1.x *= inv; x1.y *= inv; x1.z *= inv; x1.w *= inv;
    p[tid] = x0; p[tid + 256] = x1;
}

// ---------------- K3: output = attn @ V  (128q x 64d tiles, k-tile 64) -----
__global__ __launch_bounds__(256) void k3_av(
    const float* __restrict__ attn, const float* __restrict__ vg,
    float* __restrict__ outp)
{
    extern __shared__ float smx[];
    float* As = smx;              // [128][68]
    float* Vs = smx + 128 * 68;   // [64][68]
    const int tid = threadIdx.x;
    const int qt = blockIdx.x, bh = blockIdx.y;
    const int ty = tid >> 4, tx = tid & 15;
    const int qr = ty << 3, dc = tx << 2;

    float2 acc[8][2];
#pragma unroll
    for (int i = 0; i < 8; i++) { acc[i][0] = make_float2(0.f,0.f); acc[i][1] = make_float2(0.f,0.f); }

    for (int kt = 0; kt < 32; kt++) {
        const float4* asrc = (const float4*)(attn + ((size_t)bh * SS + (size_t)qt * 128) * SS + kt * 64);
        const float4* vsrc = (const float4*)(vg + ((size_t)bh * SS + (size_t)kt * 64) * DD);
#pragma unroll
        for (int rep = 0; rep < 8; rep++) {
            int i4 = rep * 256 + tid;
            int row = i4 >> 4, c4 = (i4 & 15) << 2;
            *(float4*)(As + row * 68 + c4) = asrc[row * 512 + (c4 >> 2)];
        }
#pragma unroll
        for (int rep = 0; rep < 4; rep++) {
            int i4 = rep * 256 + tid;
            int row = i4 >> 4, c4 = (i4 & 15) << 2;
            *(float4*)(Vs + row * 68 + c4) = vsrc[row * 16 + (c4 >> 2)];
        }
        __syncthreads();

#pragma unroll 4
        for (int k4 = 0; k4 < 16; k4++) {
            int kk = k4 << 2;
            float4 vr[4];
#pragma unroll
            for (int t = 0; t < 4; t++) vr[t] = *(const float4*)(Vs + (kk + t) * 68 + dc);
#pragma unroll
            for (int i = 0; i < 8; i++) {
                float4 a = *(const float4*)(As + (qr + i) * 68 + kk);
                float2 a0 = make_float2(a.x, a.x), a1 = make_float2(a.y, a.y);
                float2 a2 = make_float2(a.z, a.z), a3 = make_float2(a.w, a.w);
                acc[i][0] = ffma2(a0, make_float2(vr[0].x, vr[0].y), acc[i][0]);
                acc[i][1] = ffma2(a0, make_float2(vr[0].z, vr[0].w), acc[i][1]);
                acc[i][0] = ffma2(a1, make_float2(vr[1].x, vr[1].y), acc[i][0]);
                acc[i][1] = ffma2(a1, make_float2(vr[1].z, vr[1].w), acc[i][1]);
                acc[i][0] = ffma2(a2, make_float2(vr[2].x, vr[2].y), acc[i][0]);
                acc[i][1] = ffma2(a2, make_float2(vr[2].z, vr[2].w), acc[i][1]);
                acc[i][0] = ffma2(a3, make_float2(vr[3].x, vr[3].y), acc[i][0]);
                acc[i][1] = ffma2(a3, make_float2(vr[3].z, vr[3].w), acc[i][1]);
            }
        }
        __syncthreads();
    }

#pragma unroll
    for (int i = 0; i < 8; i++) {
        size_t off = ((size_t)bh * SS + (size_t)qt * 128 + qr + i) * DD + dc;
        *(float4*)(outp + off) =
            make_float4(acc[i][0].x, acc[i][0].y, acc[i][1].x, acc[i][1].y);
    }
}

extern "C" void kernel_launch(void* const* d_in, const int* in_sizes, int n_in,
                              void* d_out, int out_size)
{
    const float* q  = (const float*)d_in[0];
    const float* k  = (const float*)d_in[1];
    const float* v  = (const float*)d_in[2];
    const float* bw = (const float*)d_in[3];
    const int* ctx  = (const int*)d_in[4];
    const int* mem  = (const int*)d_in[5];
    const unsigned int* mask = (const unsigned int*)d_in[6];

    float* outp = (float*)d_out;                    // [2,16,2048,64]
    float* attn = outp + (size_t)2*16*2048*64;      // [2,16,2048,2048]
    float* pb   = attn + (size_t)2*16*2048*2048;    // [2,16,2048,2048]

    cudaFuncSetAttribute(k1_scores, cudaFuncAttributeMaxDynamicSharedMemorySize, 64*132*2*4);
    cudaFuncSetAttribute(k3_av,     cudaFuncAttributeMaxDynamicSharedMemorySize, (128*68+64*68)*4);

    dim3 g1(16, 16, 32);
    k1_scores<<<g1, 256, 64*132*2*4>>>(q, k, bw, ctx, mem, mask, attn, pb);
    k2_softmax<<<2*16*2048, 256>>>(attn);
    dim3 g3(16, 32);
    k3_av<<<g3, 256, (128*68+64*68)*4>>>(attn, v, outp);
}